// round 1
// baseline (speedup 1.0000x reference)
#include <cuda_runtime.h>
#include <cuda_bf16.h>
#include <cstdint>

// Problem constants
#define Bn 4096
#define Sn 64
#define Fn 8
#define Dn 64
#define Kn 16
#define Ln 4096   // S*D = flattened per-sample length
#define PN (Bn*Sn*Fn)   // 2097152

// ---------------- device scratch (no allocations allowed) ----------------
__device__ float           g_xenc_f32[Bn * Ln];          // 64 MB
__device__ __nv_bfloat16   g_xenc_bf16[Bn * Ln];         // 32 MB
__device__ float           g_gram[Bn * Bn];              // 64 MB
__device__ int             g_topidx[Bn * Kn];
__device__ float           g_c2[Bn];
__device__ float           g_part_mse[8192];
__device__ float           g_part_d1[Bn];
__device__ float           g_part_d2[Bn];
__device__ float           g_P[PN];                      // fallback storage for x_rec_proj

// ---------------- helpers ----------------
__device__ __forceinline__ float block_reduce_sum(float v, float* s) {
    int t = threadIdx.x;
    s[t] = v;
    __syncthreads();
    for (int k = blockDim.x >> 1; k > 0; k >>= 1) {
        if (t < k) s[t] += s[t + k];
        __syncthreads();
    }
    return s[0];
}

__device__ __forceinline__ void cp_async16(void* dst, const void* src) {
    uint32_t d = (uint32_t)__cvta_generic_to_shared(dst);
    asm volatile("cp.async.cg.shared.global [%0], [%1], 16;\n" :: "r"(d), "l"(src) : "memory");
}

__device__ __forceinline__ void mma16816(float* c, const uint32_t* a, const uint32_t* b) {
    asm volatile(
        "mma.sync.aligned.m16n8k16.row.col.f32.bf16.bf16.f32 "
        "{%0,%1,%2,%3}, {%4,%5,%6,%7}, {%8,%9}, {%0,%1,%2,%3};"
        : "+f"(c[0]), "+f"(c[1]), "+f"(c[2]), "+f"(c[3])
        : "r"(a[0]), "r"(a[1]), "r"(a[2]), "r"(a[3]), "r"(b[0]), "r"(b[1]));
}

__device__ __forceinline__ uint32_t ld_bf2(const __nv_bfloat16* p) {
    return *reinterpret_cast<const uint32_t*>(p);
}

// ---------------- 1) x_enc = x @ W_emb + b_emb  (also bf16 copy) ----------------
__global__ void embed_kernel(const float* __restrict__ x,
                             const float* __restrict__ Wemb,
                             const float* __restrict__ bemb) {
    __shared__ float sW[Fn * Dn];   // 512
    __shared__ float sb[Dn];
    int t = threadIdx.x;
    for (int i = t; i < Fn * Dn; i += blockDim.x) sW[i] = Wemb[i];
    if (t < Dn) sb[t] = bemb[t];
    __syncthreads();

    int e = blockIdx.x * 256 + t;   // e < Bn*Ln = 16777216
    int r = e >> 6;                 // sample-row (b*S + s)
    int d = e & 63;
    const float* xr = x + (size_t)r * Fn;
    float acc = sb[d];
#pragma unroll
    for (int f = 0; f < Fn; f++) acc += xr[f] * sW[f * Dn + d];
    g_xenc_f32[e]  = acc;
    g_xenc_bf16[e] = __float2bfloat16(acc);
}

// ---------------- 2) P = x_enc @ W_proj + b_proj ; mse partials ----------------
__global__ void proj_kernel(const float* __restrict__ x,
                            const float* __restrict__ Wproj,
                            const float* __restrict__ bproj,
                            float* __restrict__ P) {
    __shared__ float sW[Dn * Fn];   // 512
    __shared__ float sb[Fn];
    __shared__ float sred[256];
    int t = threadIdx.x;
    for (int i = t; i < Dn * Fn; i += blockDim.x) sW[i] = Wproj[i];
    if (t < Fn) sb[t] = bproj[t];
    __syncthreads();

    int e = blockIdx.x * 256 + t;   // e < PN
    int r = e >> 3;
    int f = e & 7;
    const float* xe = g_xenc_f32 + (size_t)r * Dn;
    float acc = sb[f];
#pragma unroll
    for (int d = 0; d < Dn; d++) acc += xe[d] * sW[d * Fn + f];
    P[e] = acc;
    float dv = acc - x[e];
    float part = block_reduce_sum(dv * dv, sred);
    if (t == 0) g_part_mse[blockIdx.x] = part;
}

// ---------------- 3) per-sample diff2 contribution c2[j] ----------------
__global__ void c2_kernel(const float* __restrict__ P) {
    int wid  = threadIdx.x >> 5;
    int lane = threadIdx.x & 31;
    int j = blockIdx.x * 4 + wid;   // one warp per sample
    const float* p = P + (size_t)j * (Sn * Fn);
    float acc = 0.f;
    for (int i = lane; i < (Sn - 1) * Fn; i += 32) {
        int s = i >> 3, f = i & 7;
        float d = p[(s + 1) * Fn + f] - p[s * Fn + f];
        acc += d * d;
    }
#pragma unroll
    for (int o = 16; o > 0; o >>= 1) acc += __shfl_down_sync(0xffffffffu, acc, o);
    if (lane == 0) g_c2[j] = acc;
}

// ---------------- 4) gram = Xe @ Xe^T  (bf16 mma.sync, fp32 accum) ----------------
// CTA tile 128x128, BK=32, double-buffered cp.async, 8 warps (2x4), warp tile 64x32.
#define GK 32
#define ROWPAD 40   // 32 elems + 8 pad -> 80B rows, conflict-free LDS.32
__global__ __launch_bounds__(256, 2) void gram_kernel() {
    __shared__ __nv_bfloat16 sh[2][2][128 * ROWPAD];   // [buf][A/B] ~40KB

    const int tid  = threadIdx.x;
    const int wid  = tid >> 5;
    const int lane = tid & 31;
    const int wm = wid >> 2;           // 0..1
    const int wn = wid & 3;            // 0..3
    const int rowBase = blockIdx.y * 128;
    const int colBase = blockIdx.x * 128;
    const __nv_bfloat16* Xe = g_xenc_bf16;

    float acc[4][4][4];
#pragma unroll
    for (int i = 0; i < 4; i++)
#pragma unroll
        for (int j = 0; j < 4; j++)
#pragma unroll
            for (int k = 0; k < 4; k++) acc[i][j][k] = 0.f;

    const int rq = lane >> 2;          // 0..7
    const int kp = (lane & 3) << 1;    // 0,2,4,6

    // tile loader: 512 granules(16B) each for A and B; 2 per thread per side
    auto load_tile = [&](int buf, int kt) {
        int k0 = kt * GK;
#pragma unroll
        for (int i = 0; i < 2; i++) {
            int c = tid + i * 256;     // 0..511
            int r = c >> 2, g = c & 3;
            cp_async16(&sh[buf][0][r * ROWPAD + g * 8],
                       Xe + (size_t)(rowBase + r) * Ln + k0 + g * 8);
            cp_async16(&sh[buf][1][r * ROWPAD + g * 8],
                       Xe + (size_t)(colBase + r) * Ln + k0 + g * 8);
        }
        asm volatile("cp.async.commit_group;\n" ::: "memory");
    };

    load_tile(0, 0);

    const int NT = Ln / GK;   // 128
    for (int kt = 0; kt < NT; kt++) {
        if (kt + 1 < NT) {
            load_tile((kt + 1) & 1, kt + 1);
            asm volatile("cp.async.wait_group 1;\n" ::: "memory");
        } else {
            asm volatile("cp.async.wait_group 0;\n" ::: "memory");
        }
        __syncthreads();

        const __nv_bfloat16* A = sh[kt & 1][0];
        const __nv_bfloat16* Bs = sh[kt & 1][1];
#pragma unroll
        for (int ks = 0; ks < 2; ks++) {
            int e0 = ks * 16 + kp;
            uint32_t a[4][4];
#pragma unroll
            for (int mt = 0; mt < 4; mt++) {
                int r0 = wm * 64 + mt * 16 + rq;
                a[mt][0] = ld_bf2(A + r0 * ROWPAD + e0);
                a[mt][1] = ld_bf2(A + (r0 + 8) * ROWPAD + e0);
                a[mt][2] = ld_bf2(A + r0 * ROWPAD + e0 + 8);
                a[mt][3] = ld_bf2(A + (r0 + 8) * ROWPAD + e0 + 8);
            }
            uint32_t bb[4][2];
#pragma unroll
            for (int nt = 0; nt < 4; nt++) {
                int n0 = wn * 32 + nt * 8 + rq;
                bb[nt][0] = ld_bf2(Bs + n0 * ROWPAD + e0);
                bb[nt][1] = ld_bf2(Bs + n0 * ROWPAD + e0 + 8);
            }
#pragma unroll
            for (int mt = 0; mt < 4; mt++)
#pragma unroll
                for (int nt = 0; nt < 4; nt++)
                    mma16816(&acc[mt][nt][0], &a[mt][0], &bb[nt][0]);
        }
        __syncthreads();
    }

    // store (coalesced-ish float2 stores)
#pragma unroll
    for (int mt = 0; mt < 4; mt++) {
#pragma unroll
        for (int nt = 0; nt < 4; nt++) {
            int row = rowBase + wm * 64 + mt * 16 + rq;
            int col = colBase + wn * 32 + nt * 8 + kp;
            float2* p0 = reinterpret_cast<float2*>(&g_gram[(size_t)row * Bn + col]);
            float2* p1 = reinterpret_cast<float2*>(&g_gram[(size_t)(row + 8) * Bn + col]);
            *p0 = make_float2(acc[mt][nt][0], acc[mt][nt][1]);
            *p1 = make_float2(acc[mt][nt][2], acc[mt][nt][3]);
        }
    }
}

// ---------------- 5) per-row top-16 (sorted desc, tie -> lower index) ----------------
__global__ void topk_kernel() {
    __shared__ float sv[Bn];        // 16KB
    __shared__ float rv[128];
    __shared__ int   ri[128];
    int b = blockIdx.x;
    int t = threadIdx.x;
    for (int i = t; i < Bn; i += 128) sv[i] = g_gram[(size_t)b * Bn + i];
    __syncthreads();
    if (t == 0) sv[b] = -INFINITY;   // exclude diagonal
    __syncthreads();

    for (int it = 0; it < Kn; it++) {
        float best = -INFINITY;
        int bi = 0;
        for (int i = t; i < Bn; i += 128) {
            float v = sv[i];
            if (v > best) { best = v; bi = i; }
        }
        rv[t] = best; ri[t] = bi;
        __syncthreads();
        for (int s = 64; s > 0; s >>= 1) {
            if (t < s) {
                if (rv[t + s] > rv[t] || (rv[t + s] == rv[t] && ri[t + s] < ri[t])) {
                    rv[t] = rv[t + s]; ri[t] = ri[t + s];
                }
            }
            __syncthreads();
        }
        if (t == 0) {
            g_topidx[b * Kn + it] = ri[0];
            sv[ri[0]] = -INFINITY;
        }
        __syncthreads();
    }
}

// ---------------- 6) diff1/diff2 partials per batch row ----------------
__global__ void diff_kernel(const float* __restrict__ P) {
    __shared__ int   idx[Kn];
    __shared__ float sred[128];
    int b = blockIdx.x;
    int t = threadIdx.x;
    if (t < Kn) idx[t] = g_topidx[b * Kn + t];
    __syncthreads();

    float a1 = 0.f;
    for (int k = 0; k < Kn - 1; k++) {
        const float* u = P + (size_t)idx[k] * (Sn * Fn);
        const float* v = P + (size_t)idx[k + 1] * (Sn * Fn);
        for (int i = t; i < Sn * Fn; i += 128) {
            float d = v[i] - u[i];
            a1 += d * d;
        }
    }
    float s1 = block_reduce_sum(a1, sred);
    if (t == 0) g_part_d1[b] = s1;
    __syncthreads();

    float a2 = (t < Kn) ? g_c2[idx[t]] : 0.f;
    float s2 = block_reduce_sum(a2, sred);
    if (t == 0) g_part_d2[b] = s2;
}

// ---------------- 7) deterministic final reduce -> loss ----------------
__global__ void final_kernel(float* __restrict__ out, int write_loss) {
    __shared__ float s[256];
    int t = threadIdx.x;
    float m = 0.f, d1 = 0.f, d2 = 0.f;
    for (int i = t; i < 8192; i += 256) m  += g_part_mse[i];
    for (int i = t; i < Bn;   i += 256) d1 += g_part_d1[i];
    for (int i = t; i < Bn;   i += 256) d2 += g_part_d2[i];

    float ms = block_reduce_sum(m, s);  __syncthreads();
    float s1 = block_reduce_sum(d1, s); __syncthreads();
    float s2 = block_reduce_sum(d2, s);
    if (t == 0 && write_loss) {
        float loss = ms / 2097152.0f
                   + s1 / 31457280.0f     // B*(K-1)*S*F
                   + s2 / 33030144.0f;    // B*K*(S-1)*F
        out[0] = loss;
    }
}

// ---------------- launch ----------------
extern "C" void kernel_launch(void* const* d_in, const int* in_sizes, int n_in,
                              void* d_out, int out_size) {
    (void)in_sizes; (void)n_in;
    const float* x     = (const float*)d_in[0];
    const float* Wemb  = (const float*)d_in[1];
    const float* bemb  = (const float*)d_in[2];
    const float* Wproj = (const float*)d_in[3];
    const float* bproj = (const float*)d_in[4];
    float* out = (float*)d_out;

    // output layout handling: (loss, x_rec_proj) flattened in return order
    float* P;
    int write_loss;
    float* Pfallback;
    cudaGetSymbolAddress((void**)&Pfallback, g_P);
    if (out_size >= PN + 1)      { P = out + 1;  write_loss = 1; }
    else if (out_size == PN)     { P = out;      write_loss = 0; }
    else                         { P = Pfallback; write_loss = 1; }

    embed_kernel<<<65536, 256>>>(x, Wemb, bemb);
    proj_kernel<<<8192, 256>>>(x, Wproj, bproj, P);
    c2_kernel<<<1024, 128>>>(P);
    gram_kernel<<<dim3(32, 32), 256>>>();
    topk_kernel<<<Bn, 128>>>();
    diff_kernel<<<Bn, 128>>>(P);
    final_kernel<<<1, 256>>>(out, write_loss);
}

// round 2
// speedup vs baseline: 1.4820x; 1.4820x over previous
#include <cuda_runtime.h>
#include <cuda_bf16.h>
#include <cstdint>

#define Bn 4096
#define Sn 64
#define Fn 8
#define Dn 64
#define Kn 16
#define Ln 4096
#define PN (Bn*Sn*Fn)

// ---------------- device scratch ----------------
__device__ __nv_bfloat16   g_xenc_bf16[Bn * Ln];         // 32 MB
__device__ float           g_gram[Bn * Bn];              // 64 MB
__device__ int             g_topidx[Bn * Kn];
__device__ float           g_c2[Bn];
__device__ float           g_part_mse[8192];
__device__ float           g_part_d1[Bn];
__device__ float           g_part_d2[Bn];
__device__ float           g_Weff[Fn * Fn];
__device__ float           g_beff[Fn];
__device__ float           g_P[PN];                      // fallback

// ---------------- helpers ----------------
__device__ __forceinline__ float block_reduce_sum(float v, float* s) {
    int t = threadIdx.x;
    s[t] = v;
    __syncthreads();
    for (int k = blockDim.x >> 1; k > 0; k >>= 1) {
        if (t < k) s[t] += s[t + k];
        __syncthreads();
    }
    return s[0];
}

__device__ __forceinline__ void cp_async16(void* dst, const void* src) {
    uint32_t d = (uint32_t)__cvta_generic_to_shared(dst);
    asm volatile("cp.async.cg.shared.global [%0], [%1], 16;\n" :: "r"(d), "l"(src) : "memory");
}

__device__ __forceinline__ void mma16816(float* c, const uint32_t* a, const uint32_t* b) {
    asm volatile(
        "mma.sync.aligned.m16n8k16.row.col.f32.bf16.bf16.f32 "
        "{%0,%1,%2,%3}, {%4,%5,%6,%7}, {%8,%9}, {%0,%1,%2,%3};"
        : "+f"(c[0]), "+f"(c[1]), "+f"(c[2]), "+f"(c[3])
        : "r"(a[0]), "r"(a[1]), "r"(a[2]), "r"(a[3]), "r"(b[0]), "r"(b[1]));
}

__device__ __forceinline__ uint32_t ld_bf2(const __nv_bfloat16* p) {
    return *reinterpret_cast<const uint32_t*>(p);
}

// value+index packing: larger value wins; on ties, smaller index wins
__device__ __forceinline__ unsigned long long pack_vi(float v, int i) {
    uint32_t b = __float_as_uint(v);
    b ^= (b >> 31) ? 0xFFFFFFFFu : 0x80000000u;
    return ((unsigned long long)b << 32) | (unsigned long long)(0xFFFFFFFFu - (uint32_t)i);
}

// ---------------- 0) W_eff = W_emb @ W_proj ; b_eff ----------------
__global__ void weff_kernel(const float* __restrict__ Wemb,
                            const float* __restrict__ bemb,
                            const float* __restrict__ Wproj,
                            const float* __restrict__ bproj) {
    int t = threadIdx.x;   // 64 threads: g = t>>3, f = t&7
    int g = t >> 3, f = t & 7;
    float acc = 0.f;
#pragma unroll
    for (int d = 0; d < Dn; d++) acc += Wemb[g * Dn + d] * Wproj[d * Fn + f];
    g_Weff[g * Fn + f] = acc;
    if (t < Fn) {
        float b = bproj[t];
        for (int d = 0; d < Dn; d++) b += bemb[d] * Wproj[d * Fn + t];
        g_beff[t] = b;
    }
}

// ---------------- 1) fused: enc(bf16) + P + mse partials ----------------
// 8 threads per row; thread (r, dg): enc d = dg*8..dg*8+7, and P[r, dg].
__global__ void fused_front_kernel(const float* __restrict__ x,
                                   const float* __restrict__ Wemb,
                                   const float* __restrict__ bemb,
                                   float* __restrict__ P) {
    __shared__ float sW[Fn * Dn];     // 512
    __shared__ float sb[Dn];
    __shared__ float sWe[Fn * Fn];
    __shared__ float sbe[Fn];
    __shared__ float sred[256];
    int t = threadIdx.x;
    for (int i = t; i < Fn * Dn; i += 256) sW[i] = Wemb[i];
    if (t < Dn) sb[t] = bemb[t];
    if (t < Fn * Fn) sWe[t] = g_Weff[t];
    if (t < Fn) sbe[t] = g_beff[t];
    __syncthreads();

    int gt = blockIdx.x * 256 + t;
    int r  = gt >> 3;
    int dg = gt & 7;
    const float* xr = x + (size_t)r * Fn;
    float xv[Fn];
#pragma unroll
    for (int f = 0; f < Fn; f++) xv[f] = xr[f];

    // enc: 8 d-values
    __nv_bfloat16 ev[8];
#pragma unroll
    for (int j = 0; j < 8; j++) {
        int d = dg * 8 + j;
        float acc = sb[d];
#pragma unroll
        for (int f = 0; f < Fn; f++) acc += xv[f] * sW[f * Dn + d];
        ev[j] = __float2bfloat16(acc);
    }
    *reinterpret_cast<uint4*>(&g_xenc_bf16[(size_t)r * Dn + dg * 8]) =
        *reinterpret_cast<uint4*>(ev);

    // P[r, f=dg]
    float p = sbe[dg];
#pragma unroll
    for (int g = 0; g < Fn; g++) p += xv[g] * sWe[g * Fn + dg];
    P[(size_t)r * Fn + dg] = p;
    float dv = p - xv[dg];
    float part = block_reduce_sum(dv * dv, sred);
    if (t == 0) g_part_mse[blockIdx.x] = part;
}

// ---------------- 2) per-sample diff2 contribution c2[j] ----------------
__global__ void c2_kernel(const float* __restrict__ P) {
    int wid  = threadIdx.x >> 5;
    int lane = threadIdx.x & 31;
    int j = blockIdx.x * 4 + wid;
    const float* p = P + (size_t)j * (Sn * Fn);
    float acc = 0.f;
    for (int i = lane; i < (Sn - 1) * Fn; i += 32) {
        float d = p[i + Fn] - p[i];
        acc += d * d;
    }
#pragma unroll
    for (int o = 16; o > 0; o >>= 1) acc += __shfl_down_sync(0xffffffffu, acc, o);
    if (lane == 0) g_c2[j] = acc;
}

// ---------------- 3) gram (symmetric): upper-tri 128x128 tiles, BK=64 ----------------
#define GK 64
#define ROWPAD 72   // 64 + 8 pad elems (144B rows, conflict-free)
#define TILE_ELEMS (128 * ROWPAD)

__global__ __launch_bounds__(256, 2) void gram_kernel() {
    extern __shared__ __nv_bfloat16 sh[];  // [2 bufs][A,B][128*ROWPAD] = 73728 B

    const int tid  = threadIdx.x;
    const int wid  = tid >> 5;
    const int lane = tid & 31;
    const int wm = wid >> 2;
    const int wn = wid & 3;

    // decode upper-triangular tile (i <= j) from linear id
    int tl = blockIdx.x;                  // 0..527
    int i = (int)((65.0f - sqrtf(65.0f * 65.0f - 8.0f * (float)tl)) * 0.5f);
    while (i * 32 - i * (i - 1) / 2 > tl) i--;
    while ((i + 1) * 32 - (i + 1) * i / 2 <= tl) i++;
    int j = i + (tl - (i * 32 - i * (i - 1) / 2));
    const int rowBase = i * 128;
    const int colBase = j * 128;
    const bool diag = (i == j);

    const __nv_bfloat16* Xe = g_xenc_bf16;

    float acc[4][4][4];
#pragma unroll
    for (int a = 0; a < 4; a++)
#pragma unroll
        for (int b = 0; b < 4; b++)
#pragma unroll
            for (int c = 0; c < 4; c++) acc[a][b][c] = 0.f;

    const int rq = lane >> 2;
    const int kp = (lane & 3) << 1;

    auto load_tile = [&](int buf, int kt) {
        int k0 = kt * GK;
        __nv_bfloat16* sA = sh + buf * (2 * TILE_ELEMS);
        __nv_bfloat16* sB = sA + TILE_ELEMS;
#pragma unroll
        for (int it = 0; it < 4; it++) {
            int c = tid + it * 256;       // 0..1023 (1024 granules of 16B per side)
            int r = c >> 3, g = c & 7;
            cp_async16(&sA[r * ROWPAD + g * 8],
                       Xe + (size_t)(rowBase + r) * Ln + k0 + g * 8);
            cp_async16(&sB[r * ROWPAD + g * 8],
                       Xe + (size_t)(colBase + r) * Ln + k0 + g * 8);
        }
        asm volatile("cp.async.commit_group;\n" ::: "memory");
    };

    load_tile(0, 0);

    const int NT = Ln / GK;   // 64
    for (int kt = 0; kt < NT; kt++) {
        if (kt + 1 < NT) {
            load_tile((kt + 1) & 1, kt + 1);
            asm volatile("cp.async.wait_group 1;\n" ::: "memory");
        } else {
            asm volatile("cp.async.wait_group 0;\n" ::: "memory");
        }
        __syncthreads();

        const __nv_bfloat16* A  = sh + (kt & 1) * (2 * TILE_ELEMS);
        const __nv_bfloat16* Bs = A + TILE_ELEMS;
#pragma unroll
        for (int ks = 0; ks < 4; ks++) {
            int e0 = ks * 16 + kp;
            uint32_t a[4][4];
#pragma unroll
            for (int mt = 0; mt < 4; mt++) {
                int r0 = wm * 64 + mt * 16 + rq;
                a[mt][0] = ld_bf2(A + r0 * ROWPAD + e0);
                a[mt][1] = ld_bf2(A + (r0 + 8) * ROWPAD + e0);
                a[mt][2] = ld_bf2(A + r0 * ROWPAD + e0 + 8);
                a[mt][3] = ld_bf2(A + (r0 + 8) * ROWPAD + e0 + 8);
            }
            uint32_t bb[4][2];
#pragma unroll
            for (int nt = 0; nt < 4; nt++) {
                int n0 = wn * 32 + nt * 8 + rq;
                bb[nt][0] = ld_bf2(Bs + n0 * ROWPAD + e0);
                bb[nt][1] = ld_bf2(Bs + n0 * ROWPAD + e0 + 8);
            }
#pragma unroll
            for (int mt = 0; mt < 4; mt++)
#pragma unroll
                for (int nt = 0; nt < 4; nt++)
                    mma16816(&acc[mt][nt][0], &a[mt][0], &bb[nt][0]);
        }
        __syncthreads();
    }

#pragma unroll
    for (int mt = 0; mt < 4; mt++) {
#pragma unroll
        for (int nt = 0; nt < 4; nt++) {
            int row = rowBase + wm * 64 + mt * 16 + rq;
            int col = colBase + wn * 32 + nt * 8 + kp;
            *reinterpret_cast<float2*>(&g_gram[(size_t)row * Bn + col]) =
                make_float2(acc[mt][nt][0], acc[mt][nt][1]);
            *reinterpret_cast<float2*>(&g_gram[(size_t)(row + 8) * Bn + col]) =
                make_float2(acc[mt][nt][2], acc[mt][nt][3]);
            if (!diag) {
                // mirror store (8 lanes with same kp give 32B-contiguous runs)
                g_gram[(size_t)col * Bn + row]           = acc[mt][nt][0];
                g_gram[(size_t)(col + 1) * Bn + row]     = acc[mt][nt][1];
                g_gram[(size_t)col * Bn + row + 8]       = acc[mt][nt][2];
                g_gram[(size_t)(col + 1) * Bn + row + 8] = acc[mt][nt][3];
            }
        }
    }
}

// ---------------- 4) per-row top-16 (desc, tie -> lower index) ----------------
__global__ void topk_kernel() {
    __shared__ float sv[Bn];        // 16KB
    __shared__ unsigned long long wmax[8];
    int b = blockIdx.x;
    int t = threadIdx.x;
    int lane = t & 31, wid = t >> 5;
    for (int i = t; i < Bn; i += 256) sv[i] = g_gram[(size_t)b * Bn + i];
    __syncthreads();
    if (t == 0) sv[b] = -INFINITY;
    __syncthreads();

    for (int it = 0; it < Kn; it++) {
        unsigned long long best = 0;
        for (int i = t; i < Bn; i += 256) {
            unsigned long long p = pack_vi(sv[i], i);
            if (p > best) best = p;
        }
#pragma unroll
        for (int o = 16; o > 0; o >>= 1) {
            unsigned long long v = __shfl_down_sync(0xffffffffu, best, o);
            if (v > best) best = v;
        }
        if (lane == 0) wmax[wid] = best;
        __syncthreads();
        if (t == 0) {
            unsigned long long bb = wmax[0];
#pragma unroll
            for (int w = 1; w < 8; w++) if (wmax[w] > bb) bb = wmax[w];
            int idx = (int)(0xFFFFFFFFu - (uint32_t)(bb & 0xFFFFFFFFull));
            g_topidx[b * Kn + it] = idx;
            sv[idx] = -INFINITY;
        }
        __syncthreads();
    }
}

// ---------------- 5) diff1/diff2 partials ----------------
__global__ void diff_kernel(const float* __restrict__ P) {
    __shared__ int   idx[Kn];
    __shared__ float sred[128];
    int b = blockIdx.x;
    int t = threadIdx.x;
    if (t < Kn) idx[t] = g_topidx[b * Kn + t];
    __syncthreads();

    float a1 = 0.f;
    for (int k = 0; k < Kn - 1; k++) {
        const float* u = P + (size_t)idx[k] * (Sn * Fn);
        const float* v = P + (size_t)idx[k + 1] * (Sn * Fn);
        for (int i = t; i < Sn * Fn; i += 128) {
            float d = v[i] - u[i];
            a1 += d * d;
        }
    }
    float s1 = block_reduce_sum(a1, sred);
    if (t == 0) g_part_d1[b] = s1;
    __syncthreads();

    float a2 = (t < Kn) ? g_c2[idx[t]] : 0.f;
    float s2 = block_reduce_sum(a2, sred);
    if (t == 0) g_part_d2[b] = s2;
}

// ---------------- 6) deterministic final reduce ----------------
__global__ void final_kernel(float* __restrict__ out, int write_loss) {
    __shared__ float s[256];
    int t = threadIdx.x;
    float m = 0.f, d1 = 0.f, d2 = 0.f;
    for (int i = t; i < 8192; i += 256) m  += g_part_mse[i];
    for (int i = t; i < Bn;   i += 256) d1 += g_part_d1[i];
    for (int i = t; i < Bn;   i += 256) d2 += g_part_d2[i];

    float ms = block_reduce_sum(m, s);  __syncthreads();
    float s1 = block_reduce_sum(d1, s); __syncthreads();
    float s2 = block_reduce_sum(d2, s);
    if (t == 0 && write_loss) {
        float loss = ms / 2097152.0f
                   + s1 / 31457280.0f
                   + s2 / 33030144.0f;
        out[0] = loss;
    }
}

// ---------------- launch ----------------
extern "C" void kernel_launch(void* const* d_in, const int* in_sizes, int n_in,
                              void* d_out, int out_size) {
    (void)in_sizes; (void)n_in;
    const float* x     = (const float*)d_in[0];
    const float* Wemb  = (const float*)d_in[1];
    const float* bemb  = (const float*)d_in[2];
    const float* Wproj = (const float*)d_in[3];
    const float* bproj = (const float*)d_in[4];
    float* out = (float*)d_out;

    float* P;
    int write_loss;
    float* Pfallback;
    cudaGetSymbolAddress((void**)&Pfallback, g_P);
    if (out_size >= PN + 1)      { P = out + 1;  write_loss = 1; }
    else if (out_size == PN)     { P = out;      write_loss = 0; }
    else                         { P = Pfallback; write_loss = 1; }

    static int smem_set = 0;
    if (!smem_set) {
        cudaFuncSetAttribute(gram_kernel,
                             cudaFuncAttributeMaxDynamicSharedMemorySize, 73728);
        smem_set = 1;
    }

    weff_kernel<<<1, 64>>>(Wemb, bemb, Wproj, bproj);
    fused_front_kernel<<<8192, 256>>>(x, Wemb, bemb, P);
    c2_kernel<<<1024, 128>>>(P);
    gram_kernel<<<528, 256, 73728>>>();
    topk_kernel<<<Bn, 256>>>();
    diff_kernel<<<Bn, 128>>>(P);
    final_kernel<<<1, 256>>>(out, write_loss);
}

// round 4
// speedup vs baseline: 1.8405x; 1.2419x over previous
#include <cuda_runtime.h>
#include <cuda_bf16.h>
#include <cstdint>

#define Bn 4096
#define Sn 64
#define Fn 8
#define Dn 64
#define Kn 16
#define Ln 4096
#define PN (Bn*Sn*Fn)

// ---------------- device scratch ----------------
__device__ __nv_bfloat16   g_xenc_bf16[Bn * Ln];         // 32 MB
__device__ float           g_gram[Bn * Bn];              // 64 MB
__device__ int             g_topidx[Bn * Kn];
__device__ float           g_c2[Bn];
__device__ float           g_part_mse[8192];
__device__ float           g_part_d1[Bn];
__device__ float           g_part_d2[Bn];
__device__ float           g_Weff[Fn * Fn];
__device__ float           g_beff[Fn];
__device__ float           g_P[PN];                      // fallback

// ---------------- helpers ----------------
__device__ __forceinline__ float block_reduce_sum(float v, float* s) {
    int t = threadIdx.x;
    s[t] = v;
    __syncthreads();
    for (int k = blockDim.x >> 1; k > 0; k >>= 1) {
        if (t < k) s[t] += s[t + k];
        __syncthreads();
    }
    return s[0];
}

__device__ __forceinline__ void cp_async16(uint32_t dst, const void* src) {
    asm volatile("cp.async.cg.shared.global [%0], [%1], 16;\n" :: "r"(dst), "l"(src) : "memory");
}

__device__ __forceinline__ void mma16816(float* c, const uint32_t* a, const uint32_t* b) {
    asm volatile(
        "mma.sync.aligned.m16n8k16.row.col.f32.bf16.bf16.f32 "
        "{%0,%1,%2,%3}, {%4,%5,%6,%7}, {%8,%9}, {%0,%1,%2,%3};"
        : "+f"(c[0]), "+f"(c[1]), "+f"(c[2]), "+f"(c[3])
        : "r"(a[0]), "r"(a[1]), "r"(a[2]), "r"(a[3]), "r"(b[0]), "r"(b[1]));
}

__device__ __forceinline__ void ldsm_x4(uint32_t* r, uint32_t addr) {
    asm volatile("ldmatrix.sync.aligned.m8n8.x4.shared.b16 {%0,%1,%2,%3}, [%4];"
                 : "=r"(r[0]), "=r"(r[1]), "=r"(r[2]), "=r"(r[3]) : "r"(addr));
}

__device__ __forceinline__ unsigned long long pack_vi(float v, int i) {
    uint32_t b = __float_as_uint(v);
    b ^= (b >> 31) ? 0xFFFFFFFFu : 0x80000000u;
    return ((unsigned long long)b << 32) | (unsigned long long)(0xFFFFFFFFu - (uint32_t)i);
}

// ---------------- 0) W_eff = W_emb @ W_proj ; b_eff ----------------
__global__ void weff_kernel(const float* __restrict__ Wemb,
                            const float* __restrict__ bemb,
                            const float* __restrict__ Wproj,
                            const float* __restrict__ bproj) {
    int t = threadIdx.x;
    int g = t >> 3, f = t & 7;
    float acc = 0.f;
#pragma unroll
    for (int d = 0; d < Dn; d++) acc += Wemb[g * Dn + d] * Wproj[d * Fn + f];
    g_Weff[g * Fn + f] = acc;
    if (t < Fn) {
        float b = bproj[t];
        for (int d = 0; d < Dn; d++) b += bemb[d] * Wproj[d * Fn + t];
        g_beff[t] = b;
    }
}

// ---------------- 1) fused: enc(bf16) + P + mse partials ----------------
__global__ void fused_front_kernel(const float* __restrict__ x,
                                   const float* __restrict__ Wemb,
                                   const float* __restrict__ bemb,
                                   float* __restrict__ P) {
    __shared__ float sW[Fn * Dn];
    __shared__ float sb[Dn];
    __shared__ float sWe[Fn * Fn];
    __shared__ float sbe[Fn];
    __shared__ float sred[256];
    int t = threadIdx.x;
    for (int i = t; i < Fn * Dn; i += 256) sW[i] = Wemb[i];
    if (t < Dn) sb[t] = bemb[t];
    if (t < Fn * Fn) sWe[t] = g_Weff[t];
    if (t < Fn) sbe[t] = g_beff[t];
    __syncthreads();

    int gt = blockIdx.x * 256 + t;
    int r  = gt >> 3;
    int dg = gt & 7;
    const float* xr = x + (size_t)r * Fn;
    float xv[Fn];
#pragma unroll
    for (int f = 0; f < Fn; f++) xv[f] = xr[f];

    __nv_bfloat16 ev[8];
#pragma unroll
    for (int j = 0; j < 8; j++) {
        int d = dg * 8 + j;
        float acc = sb[d];
#pragma unroll
        for (int f = 0; f < Fn; f++) acc += xv[f] * sW[f * Dn + d];
        ev[j] = __float2bfloat16(acc);
    }
    *reinterpret_cast<uint4*>(&g_xenc_bf16[(size_t)r * Dn + dg * 8]) =
        *reinterpret_cast<uint4*>(ev);

    float p = sbe[dg];
#pragma unroll
    for (int g = 0; g < Fn; g++) p += xv[g] * sWe[g * Fn + dg];
    P[(size_t)r * Fn + dg] = p;
    float dv = p - xv[dg];
    float part = block_reduce_sum(dv * dv, sred);
    if (t == 0) g_part_mse[blockIdx.x] = part;
}

// ---------------- 2) per-sample diff2 contribution ----------------
__global__ void c2_kernel(const float* __restrict__ P) {
    int wid  = threadIdx.x >> 5;
    int lane = threadIdx.x & 31;
    int j = blockIdx.x * 4 + wid;
    const float* p = P + (size_t)j * (Sn * Fn);
    float acc = 0.f;
    for (int i = lane; i < (Sn - 1) * Fn; i += 32) {
        float d = p[i + Fn] - p[i];
        acc += d * d;
    }
#pragma unroll
    for (int o = 16; o > 0; o >>= 1) acc += __shfl_down_sync(0xffffffffu, acc, o);
    if (lane == 0) g_c2[j] = acc;
}

// ---------------- 3) gram (symmetric, mma.sync + ldmatrix), BK=64 ----------------
#define GK 64
#define ROWPAD 72   // 64 + 8 pad elems (144B = 9*16B rows; ldmatrix conflict-free)
#define TILE_ELEMS (128 * ROWPAD)

__global__ __launch_bounds__(256, 2) void gram_kernel() {
    extern __shared__ __nv_bfloat16 sh[];  // [2 bufs][A,B][128*ROWPAD] = 73728 B
    const uint32_t shbase = (uint32_t)__cvta_generic_to_shared(sh);

    const int tid  = threadIdx.x;
    const int wid  = tid >> 5;
    const int lane = tid & 31;
    const int wm = wid >> 2;
    const int wn = wid & 3;

    // decode upper-triangular tile (i <= j)
    int tl = blockIdx.x;                  // 0..527
    int i = (int)((65.0f - sqrtf(65.0f * 65.0f - 8.0f * (float)tl)) * 0.5f);
    while (i * 32 - i * (i - 1) / 2 > tl) i--;
    while ((i + 1) * 32 - (i + 1) * i / 2 <= tl) i++;
    int j = i + (tl - (i * 32 - i * (i - 1) / 2));
    const int rowBase = i * 128;
    const int colBase = j * 128;
    const bool diag = (i == j);

    const __nv_bfloat16* Xe = g_xenc_bf16;

    float acc[4][4][4];
#pragma unroll
    for (int a = 0; a < 4; a++)
#pragma unroll
        for (int b = 0; b < 4; b++)
#pragma unroll
            for (int c = 0; c < 4; c++) acc[a][b][c] = 0.f;

    auto load_tile = [&](int buf, int kt) {
        int k0 = kt * GK;
        uint32_t sA = shbase + (uint32_t)(buf * 2 * TILE_ELEMS) * 2u;
        uint32_t sB = sA + TILE_ELEMS * 2u;
#pragma unroll
        for (int it = 0; it < 4; it++) {
            int c = tid + it * 256;       // 0..1023
            int r = c >> 3, g = c & 7;
            cp_async16(sA + (uint32_t)(r * ROWPAD + g * 8) * 2u,
                       Xe + (size_t)(rowBase + r) * Ln + k0 + g * 8);
            cp_async16(sB + (uint32_t)(r * ROWPAD + g * 8) * 2u,
                       Xe + (size_t)(colBase + r) * Ln + k0 + g * 8);
        }
        asm volatile("cp.async.commit_group;\n" ::: "memory");
    };

    load_tile(0, 0);

    // ldmatrix lane-address components (element offsets within a tile)
    const int aRow = lane & 15;            // row within 16-row A tile
    const int aCol = (lane >> 4) << 3;     // 0 or 8 (k halves)
    const int bRow = ((lane >> 4) << 3) + (lane & 7);  // row within 16-row B pair
    const int bCol = ((lane >> 3) & 1) << 3;           // 0 or 8

    const int NT = Ln / GK;   // 64
    for (int kt = 0; kt < NT; kt++) {
        if (kt + 1 < NT) {
            load_tile((kt + 1) & 1, kt + 1);
            asm volatile("cp.async.wait_group 1;\n" ::: "memory");
        } else {
            asm volatile("cp.async.wait_group 0;\n" ::: "memory");
        }
        __syncthreads();

        uint32_t A  = shbase + (uint32_t)((kt & 1) * 2 * TILE_ELEMS) * 2u;
        uint32_t Bs = A + TILE_ELEMS * 2u;
#pragma unroll
        for (int ks = 0; ks < 4; ks++) {
            int e0 = ks * 16;
            uint32_t a[4][4];
#pragma unroll
            for (int mt = 0; mt < 4; mt++) {
                int r0 = wm * 64 + mt * 16;
                ldsm_x4(a[mt], A + (uint32_t)((r0 + aRow) * ROWPAD + e0 + aCol) * 2u);
            }
            uint32_t bb[4][2];
#pragma unroll
            for (int p = 0; p < 2; p++) {
                int n0 = wn * 32 + p * 16;
                uint32_t tmp[4];
                ldsm_x4(tmp, Bs + (uint32_t)((n0 + bRow) * ROWPAD + e0 + bCol) * 2u);
                bb[p * 2][0] = tmp[0];     bb[p * 2][1] = tmp[1];
                bb[p * 2 + 1][0] = tmp[2]; bb[p * 2 + 1][1] = tmp[3];
            }
#pragma unroll
            for (int mt = 0; mt < 4; mt++)
#pragma unroll
                for (int nt = 0; nt < 4; nt++)
                    mma16816(&acc[mt][nt][0], &a[mt][0], &bb[nt][0]);
        }
        __syncthreads();
    }

    const int rq = lane >> 2;
    const int kp = (lane & 3) << 1;
#pragma unroll
    for (int mt = 0; mt < 4; mt++) {
#pragma unroll
        for (int nt = 0; nt < 4; nt++) {
            int row = rowBase + wm * 64 + mt * 16 + rq;
            int col = colBase + wn * 32 + nt * 8 + kp;
            *reinterpret_cast<float2*>(&g_gram[(size_t)row * Bn + col]) =
                make_float2(acc[mt][nt][0], acc[mt][nt][1]);
            *reinterpret_cast<float2*>(&g_gram[(size_t)(row + 8) * Bn + col]) =
                make_float2(acc[mt][nt][2], acc[mt][nt][3]);
            if (!diag) {
                g_gram[(size_t)col * Bn + row]           = acc[mt][nt][0];
                g_gram[(size_t)(col + 1) * Bn + row]     = acc[mt][nt][1];
                g_gram[(size_t)col * Bn + row + 8]       = acc[mt][nt][2];
                g_gram[(size_t)(col + 1) * Bn + row + 8] = acc[mt][nt][3];
            }
        }
    }
}

// ---------------- 4) per-row top-16, register-resident ----------------
__global__ void topk_kernel() {
    __shared__ unsigned long long wmax[8];
    const int b = blockIdx.x;
    const int t = threadIdx.x;
    const int lane = t & 31, wid = t >> 5;

    float r[16];
    const float* row = &g_gram[(size_t)b * Bn + t * 16];
#pragma unroll
    for (int q = 0; q < 4; q++) {
        float4 v = reinterpret_cast<const float4*>(row)[q];
        r[q * 4] = v.x; r[q * 4 + 1] = v.y; r[q * 4 + 2] = v.z; r[q * 4 + 3] = v.w;
    }
    if ((b >> 4) == t) r[b & 15] = -INFINITY;   // exclude diagonal

    unsigned long long loc = pack_vi(r[0], t * 16);
#pragma unroll
    for (int q = 1; q < 16; q++) {
        unsigned long long p = pack_vi(r[q], t * 16 + q);
        if (p > loc) loc = p;
    }

    for (int it = 0; it < Kn; it++) {
        unsigned long long best = loc;
#pragma unroll
        for (int o = 16; o > 0; o >>= 1) {
            unsigned long long v = __shfl_down_sync(0xffffffffu, best, o);
            if (v > best) best = v;
        }
        if (lane == 0) wmax[wid] = best;
        __syncthreads();
        best = wmax[0];
#pragma unroll
        for (int w = 1; w < 8; w++) if (wmax[w] > best) best = wmax[w];
        const int idx = (int)(0xFFFFFFFFu - (uint32_t)(best & 0xFFFFFFFFull));
        if (t == 0) g_topidx[b * Kn + it] = idx;
        if ((idx >> 4) == t) {
#pragma unroll
            for (int q = 0; q < 16; q++) if ((idx & 15) == q) r[q] = -INFINITY;
            loc = pack_vi(r[0], t * 16);
#pragma unroll
            for (int q = 1; q < 16; q++) {
                unsigned long long p = pack_vi(r[q], t * 16 + q);
                if (p > loc) loc = p;
            }
        }
        __syncthreads();
    }
}

// ---------------- 5) diff1/diff2 partials ----------------
__global__ void diff_kernel(const float* __restrict__ P) {
    __shared__ int   idx[Kn];
    __shared__ float sred[128];
    int b = blockIdx.x;
    int t = threadIdx.x;
    if (t < Kn) idx[t] = g_topidx[b * Kn + t];
    __syncthreads();

    float a1 = 0.f;
    for (int k = 0; k < Kn - 1; k++) {
        const float* u = P + (size_t)idx[k] * (Sn * Fn);
        const float* v = P + (size_t)idx[k + 1] * (Sn * Fn);
        for (int i = t; i < Sn * Fn; i += 128) {
            float d = v[i] - u[i];
            a1 += d * d;
        }
    }
    float s1 = block_reduce_sum(a1, sred);
    if (t == 0) g_part_d1[b] = s1;
    __syncthreads();

    float a2 = (t < Kn) ? g_c2[idx[t]] : 0.f;
    float s2 = block_reduce_sum(a2, sred);
    if (t == 0) g_part_d2[b] = s2;
}

// ---------------- 6) deterministic final reduce ----------------
__global__ void final_kernel(float* __restrict__ out, int write_loss) {
    __shared__ float s[256];
    int t = threadIdx.x;
    float m = 0.f, d1 = 0.f, d2 = 0.f;
    for (int i = t; i < 8192; i += 256) m  += g_part_mse[i];
    for (int i = t; i < Bn;   i += 256) d1 += g_part_d1[i];
    for (int i = t; i < Bn;   i += 256) d2 += g_part_d2[i];

    float ms = block_reduce_sum(m, s);  __syncthreads();
    float s1 = block_reduce_sum(d1, s); __syncthreads();
    float s2 = block_reduce_sum(d2, s);
    if (t == 0 && write_loss) {
        float loss = ms / 2097152.0f
                   + s1 / 31457280.0f
                   + s2 / 33030144.0f;
        out[0] = loss;
    }
}

// ---------------- launch ----------------
extern "C" void kernel_launch(void* const* d_in, const int* in_sizes, int n_in,
                              void* d_out, int out_size) {
    (void)in_sizes; (void)n_in;
    const float* x     = (const float*)d_in[0];
    const float* Wemb  = (const float*)d_in[1];
    const float* bemb  = (const float*)d_in[2];
    const float* Wproj = (const float*)d_in[3];
    const float* bproj = (const float*)d_in[4];
    float* out = (float*)d_out;

    float* P;
    int write_loss;
    float* Pfallback;
    cudaGetSymbolAddress((void**)&Pfallback, g_P);
    if (out_size >= PN + 1)      { P = out + 1;  write_loss = 1; }
    else if (out_size == PN)     { P = out;      write_loss = 0; }
    else                         { P = Pfallback; write_loss = 1; }

    static int smem_set = 0;
    if (!smem_set) {
        cudaFuncSetAttribute(gram_kernel,
                             cudaFuncAttributeMaxDynamicSharedMemorySize, 73728);
        smem_set = 1;
    }

    weff_kernel<<<1, 64>>>(Wemb, bemb, Wproj, bproj);
    fused_front_kernel<<<8192, 256>>>(x, Wemb, bemb, P);
    c2_kernel<<<1024, 128>>>(P);
    gram_kernel<<<528, 256, 73728>>>();
    topk_kernel<<<Bn, 256>>>();
    diff_kernel<<<Bn, 128>>>(P);
    final_kernel<<<1, 256>>>(out, write_loss);
}